// round 8
// baseline (speedup 1.0000x reference)
#include <cuda_runtime.h>

// ----------------------------------------------------------------------------
// SigNet: depth-4 path signature (B=128, S=1024, C=8) + linear head (256).
//
//   1. sig_chunk_kernel  : 2048 blocks x 256 thr; 64-step chunk signatures.
//                          Thread owns (a,b) and a c-PAIR; K/s3 recursions in
//                          packed f32x2; A1-folds precomputed as prefix tables.
//   2. sig_combine_kernel: 128 blocks, Chen-combine the 16 chunk signatures.
//   3. gemm_part_kernel  : split-k GEMM  y_part = sig @ W^T   (deterministic)
//   4. reduce_kernel     : sum k-partials + bias -> out  (float4)
// ----------------------------------------------------------------------------

#define BB      128
#define SS      1024
#define CIN     7
#define NCHUNK  16
#define CL      64          // SS / NCHUNK
#define SIGCH   4680        // 8 + 64 + 512 + 4096
#define OFF2    8
#define OFF3    72
#define OFF4    584
#define DOUT    256
#define KSPLIT  24          // 24 * 195 = 4680 exactly

typedef unsigned long long ull;

__device__ float g_csig[(size_t)BB * NCHUNK * SIGCH];   // ~38 MB chunk sigs
__device__ float g_sig[(size_t)BB * SIGCH];             // combined sigs
__device__ float g_part[(size_t)KSPLIT * BB * DOUT];    // gemm partials

__device__ __forceinline__ ull f2pack(float x) {
    ull r; asm("mov.b64 %0, {%1, %1};" : "=l"(r) : "f"(x)); return r;
}
__device__ __forceinline__ void f2unpack(ull p, float& lo, float& hi) {
    asm("mov.b64 {%0, %1}, %2;" : "=f"(lo), "=f"(hi) : "l"(p));
}
__device__ __forceinline__ void f2fma(ull& d, ull a, ull b) {
    asm("fma.rn.f32x2 %0, %1, %2, %0;" : "+l"(d) : "l"(a), "l"(b));
}
__device__ __forceinline__ ull f2mul(ull a, ull b) {
    ull d; asm("mul.rn.f32x2 %0, %1, %2;" : "=l"(d) : "l"(a), "l"(b)); return d;
}

// ---------------------------------------------------------------------------
// Kernel 1: chunk signature scan.
// t -> cp = t&3 (c-pair: c0=2cp, c1=2cp+1), ab = t>>2, b = ab&7, a = ab>>3.
// State: s4 of (a,b,c0,*) and (a,b,c1,*) in 8 packed regs; s3 pair packed;
// A2[ab] scalar. A1 folds come from prefix tables q4/q3/q2[s][a].
// Per step:  Kp  = s3p + A2*vh_c + q4*(vb*v6_c)          (packed)
//            s4 += v_d * K                                (8 x fma.f32x2)
//            s3p += A2*v_c + q3*(vb*vh_c)                 (packed)
//            A2  += q2*vb
// min_blocks=3 (NOT 4): 85-reg budget avoids inner-loop spills; 24 warps/SM
// is still ample for a compute-bound loop.
// ---------------------------------------------------------------------------
__global__ __launch_bounds__(256, 3) void sig_chunk_kernel(const float* __restrict__ inp)
{
    const int blk = blockIdx.x;
    const int b   = blk >> 4;          // / NCHUNK
    const int ch  = blk & (NCHUNK - 1);
    const int t   = threadIdx.x;

    __shared__ __align__(16) float vrow[CL * 8];    // raw increments
    __shared__ __align__(16) float vhrow[CL * 8];   // v/2
    __shared__ __align__(16) float v6row[CL * 8];   // v/6
    __shared__ ull   vbp[CL * 8];                   // {v, v} per (s, chan)
    __shared__ ull   q4t[CL * 8];                   // {q4,q4} per (s, a)
    __shared__ ull   q3t[CL * 8];                   // {q3,q3}
    __shared__ float q2t[CL * 8];                   // q2 scalar per (s, a)
    __shared__ float A1fin[8];

    // --- raw increments (coalesced-ish) ---
    #pragma unroll
    for (int i = t; i < CL * CIN; i += 256) {
        int s_ = i / CIN, c_ = i % CIN;
        int g  = ch * CL + s_;
        float x  = inp[(b * SS + g) * CIN + c_];
        float xp = (g == 0) ? 0.0f : inp[(b * SS + g - 1) * CIN + c_];
        vrow[s_ * 8 + c_ + 1] = x - xp;
    }
    if (t < CL) vrow[t * 8] = (ch == 0 && t == 0) ? 0.0f : (1.0f / 1023.0f);
    __syncthreads();

    // --- derived rows ---
    #pragma unroll
    for (int i = t; i < CL * 8; i += 256) {
        float v = vrow[i];
        vhrow[i] = 0.5f * v;
        v6row[i] = v * (1.0f / 6.0f);
        vbp[i]   = f2pack(v);
    }
    // --- prefix fold tables (8 serial chains over 64 steps) ---
    if (t < 8) {
        float A1 = 0.0f;
        #pragma unroll
        for (int s = 0; s < CL; s++) {
            float va = vrow[s * 8 + t];
            q4t[s * 8 + t] = f2pack(fmaf(0.25f,       va, A1));
            q3t[s * 8 + t] = f2pack(fmaf(1.0f / 3.0f, va, A1));
            q2t[s * 8 + t] = fmaf(0.5f, va, A1);
            A1 += va;
        }
        A1fin[t] = A1;
    }
    __syncthreads();

    const int cp = t & 3;
    const int ab = t >> 2;
    const int bq = ab & 7;
    const int a  = ab >> 3;

    ull s4a[4] = {0ull, 0ull, 0ull, 0ull};
    ull s4b[4] = {0ull, 0ull, 0ull, 0ull};
    ull s3p = 0ull;
    float A2 = 0.0f;

    #pragma unroll 4
    for (int s = 0; s < CL; s++) {
        const int r = s * 8;
        ull vh64 = *(const ull*)&vhrow[r + 2 * cp];
        ull v664 = *(const ull*)&v6row[r + 2 * cp];
        ull vc64 = *(const ull*)&vrow[r + 2 * cp];
        ull vb2  = vbp[r + bq];
        ull q4b  = q4t[r + a];
        ull q3b  = q3t[r + a];
        float q2 = q2t[r + a];
        ull v01 = *(const ull*)&vrow[r + 0];
        ull v23 = *(const ull*)&vrow[r + 2];
        ull v45 = *(const ull*)&vrow[r + 4];
        ull v67 = *(const ull*)&vrow[r + 6];

        ull A2b = f2pack(A2);
        ull tt6 = f2mul(vb2, v664);
        ull tt2 = f2mul(vb2, vh64);

        ull Kp = s3p;                 // old s3
        f2fma(Kp, A2b, vh64);
        f2fma(Kp, q4b, tt6);

        f2fma(s3p, A2b, vc64);        // old A2
        f2fma(s3p, q3b, tt2);

        float vblo, vbhi;
        f2unpack(vb2, vblo, vbhi);
        A2 = fmaf(q2, vblo, A2);

        float k0, k1;
        f2unpack(Kp, k0, k1);
        ull K0 = f2pack(k0);
        ull K1 = f2pack(k1);
        f2fma(s4a[0], v01, K0); f2fma(s4a[1], v23, K0);
        f2fma(s4a[2], v45, K0); f2fma(s4a[3], v67, K0);
        f2fma(s4b[0], v01, K1); f2fma(s4b[1], v23, K1);
        f2fma(s4b[2], v45, K1); f2fma(s4b[3], v67, K1);
    }

    // write chunk signature: [L1 | L2 | L3 | L4]
    float* out = &g_csig[(size_t)(b * NCHUNK + ch) * SIGCH];
    if (t < 8)   out[t] = A1fin[t];
    if (cp == 0) out[OFF2 + ab] = A2;
    {
        float s3lo, s3hi;
        f2unpack(s3p, s3lo, s3hi);
        out[OFF3 + ab * 8 + 2 * cp]     = s3lo;
        out[OFF3 + ab * 8 + 2 * cp + 1] = s3hi;
    }
    ull* o64 = (ull*)(out + OFF4 + ab * 64 + cp * 16);
    o64[0] = s4a[0]; o64[1] = s4a[1]; o64[2] = s4a[2]; o64[3] = s4a[3];
    o64[4] = s4b[0]; o64[5] = s4b[1]; o64[6] = s4b[2]; o64[7] = s4b[3];
}

// ---------------------------------------------------------------------------
// Kernel 2: Chen-combine the NCHUNK chunk signatures (left-to-right).
// ---------------------------------------------------------------------------
__global__ __launch_bounds__(512) void sig_combine_kernel()
{
    const int b = blockIdx.x;
    const int t = threadIdx.x;
    __shared__ float R[SIGCH];
    __shared__ float X[SIGCH];

    const float* src = &g_csig[(size_t)b * NCHUNK * SIGCH];
    for (int i = t; i < SIGCH; i += 512) R[i] = src[i];

    const int a  = t >> 6;
    const int bq = (t >> 3) & 7;
    const int cq = t & 7;
    const int ab = t >> 3;

    for (int cidx = 1; cidx < NCHUNK; cidx++) {
        __syncthreads();
        const float* xs = src + (size_t)cidx * SIGCH;
        for (int i = t; i < SIGCH; i += 512) X[i] = xs[i];
        __syncthreads();

        float r1 = R[a];
        float r2 = R[OFF2 + ab];
        float r3 = R[OFF3 + t];

        #pragma unroll
        for (int d = 0; d < 8; d++) {
            float acc = R[OFF4 + t * 8 + d] + X[OFF4 + t * 8 + d];
            acc = fmaf(r1, X[OFF3 + (bq * 8 + cq) * 8 + d], acc);
            acc = fmaf(r2, X[OFF2 + cq * 8 + d], acc);
            acc = fmaf(r3, X[d], acc);
            R[OFF4 + t * 8 + d] = acc;
        }
        float acc3 = r3 + X[OFF3 + t];
        acc3 = fmaf(r1, X[OFF2 + bq * 8 + cq], acc3);
        acc3 = fmaf(r2, X[cq], acc3);
        R[OFF3 + t] = acc3;
        __syncthreads();

        if (t < 64) {
            float acc2 = R[OFF2 + t] + X[OFF2 + t];
            acc2 = fmaf(R[t >> 3], X[t & 7], acc2);
            R[OFF2 + t] = acc2;
        }
        __syncthreads();

        if (t < 8) R[t] += X[t];
    }
    __syncthreads();

    float* dst = &g_sig[(size_t)b * SIGCH];
    for (int i = t; i < SIGCH; i += 512) dst[i] = R[i];
}

// ---------------------------------------------------------------------------
// Kernel 3: split-k GEMM partials (deterministic, no atomics)
// ---------------------------------------------------------------------------
__global__ __launch_bounds__(256) void gemm_part_kernel(const float* __restrict__ W)
{
    const int otile = blockIdx.x;           // 0..7
    const int kid   = blockIdx.y;           // 0..KSPLIT-1
    const int KC    = SIGCH / KSPLIT;       // 195
    const int kbeg  = kid * KC;
    const int kend  = kbeg + KC;

    __shared__ float Ws[32][33];
    __shared__ float Sg[BB][33];

    const int tid = threadIdx.x;
    const int ox  = tid & 7;
    const int by  = tid >> 3;

    float acc[4][4];
    #pragma unroll
    for (int i = 0; i < 4; i++)
        #pragma unroll
        for (int j = 0; j < 4; j++) acc[i][j] = 0.0f;

    for (int k0 = kbeg; k0 < kend; k0 += 32) {
        for (int i = tid; i < 32 * 32; i += 256) {
            int o = i >> 5, kk = i & 31;
            int k = k0 + kk;
            Ws[o][kk] = (k < kend) ? W[(otile * 32 + o) * SIGCH + k] : 0.0f;
        }
        for (int i = tid; i < BB * 32; i += 256) {
            int bb2 = i >> 5, kk = i & 31;
            int k = k0 + kk;
            Sg[bb2][kk] = (k < kend) ? g_sig[(size_t)bb2 * SIGCH + k] : 0.0f;
        }
        __syncthreads();
        #pragma unroll 8
        for (int kk = 0; kk < 32; kk++) {
            float wv[4], sv[4];
            #pragma unroll
            for (int j = 0; j < 4; j++) wv[j] = Ws[ox * 4 + j][kk];
            #pragma unroll
            for (int i = 0; i < 4; i++) sv[i] = Sg[by * 4 + i][kk];
            #pragma unroll
            for (int i = 0; i < 4; i++)
                #pragma unroll
                for (int j = 0; j < 4; j++)
                    acc[i][j] = fmaf(sv[i], wv[j], acc[i][j]);
        }
        __syncthreads();
    }

    float* dst = &g_part[(size_t)kid * BB * DOUT];
    #pragma unroll
    for (int i = 0; i < 4; i++)
        #pragma unroll
        for (int j = 0; j < 4; j++)
            dst[(by * 4 + i) * DOUT + otile * 32 + ox * 4 + j] = acc[i][j];
}

// ---------------------------------------------------------------------------
// Kernel 4: reduce k-partials + bias -> out  (float4, deterministic order)
// ---------------------------------------------------------------------------
__global__ __launch_bounds__(128) void reduce_kernel(const float* __restrict__ bias,
                                                     float* __restrict__ out)
{
    int i4   = blockIdx.x * 128 + threadIdx.x;      // < 8192
    int base = i4 * 4;
    float4 acc = *(const float4*)&bias[base & (DOUT - 1)];
    #pragma unroll
    for (int k = 0; k < KSPLIT; k++) {
        float4 p = *(const float4*)&g_part[(size_t)k * BB * DOUT + base];
        acc.x += p.x; acc.y += p.y; acc.z += p.z; acc.w += p.w;
    }
    *(float4*)&out[base] = acc;
}

// ---------------------------------------------------------------------------
extern "C" void kernel_launch(void* const* d_in, const int* in_sizes, int n_in,
                              void* d_out, int out_size)
{
    const float* inp  = (const float*)d_in[0];   // (128, 1024, 7)
    const float* W    = (const float*)d_in[1];   // (256, 4680)
    const float* bias = (const float*)d_in[2];   // (256,)
    float* out        = (float*)d_out;           // (128, 256)
    (void)in_sizes; (void)n_in; (void)out_size;

    sig_chunk_kernel<<<BB * NCHUNK, 256>>>(inp);
    sig_combine_kernel<<<BB, 512>>>();
    dim3 gg(8, KSPLIT);
    gemm_part_kernel<<<gg, 256>>>(W);
    reduce_kernel<<<(BB * DOUT) / 512, 128>>>(bias, out);
}

// round 12
// speedup vs baseline: 1.1692x; 1.1692x over previous
#include <cuda_runtime.h>

// ----------------------------------------------------------------------------
// SigNet: depth-4 path signature (B=128, S=1024, C=8) + linear head (256).
//
//   0. noop_kernel x3   : steer ncu's "-s 5 -c 1" capture slot onto the scan.
//   1. sig_chunk_kernel  : 1024 blocks x 128 thr; each block does TWO 64-step
//                          chunks (half-block each). Thread owns a full (a,b)
//                          row: 64 level-4 entries in 32 packed f32x2 regs.
//                          1.39 issue-slots/entry vs 2.0 before (x0.70 work).
//   2. sig_combine_kernel: 128 blocks, Chen-combine (X prefetch double-buffer).
//   3. gemm_part_kernel  : split-k GEMM  y_part = sig @ W^T   (deterministic)
//   4. reduce_kernel     : sum k-partials + bias -> out (1 elem/thread)
// ----------------------------------------------------------------------------

#define BB      128
#define SS      1024
#define CIN     7
#define NCHUNK  16
#define CL      64          // SS / NCHUNK
#define SIGCH   4680        // 8 + 64 + 512 + 4096
#define OFF2    8
#define OFF3    72
#define OFF4    584
#define DOUT    256
#define KSPLIT  24          // 24 * 195 = 4680 exactly

typedef unsigned long long ull;

__device__ float g_csig[(size_t)BB * NCHUNK * SIGCH];   // ~38 MB chunk sigs
__device__ float g_sig[(size_t)BB * SIGCH];             // combined sigs
__device__ float g_part[(size_t)KSPLIT * BB * DOUT];    // gemm partials

__device__ __forceinline__ ull f2pack(float x) {
    ull r; asm("mov.b64 %0, {%1, %1};" : "=l"(r) : "f"(x)); return r;
}
__device__ __forceinline__ ull f2pack2(float lo, float hi) {
    ull r; asm("mov.b64 %0, {%1, %2};" : "=l"(r) : "f"(lo), "f"(hi)); return r;
}
__device__ __forceinline__ void f2unpack(ull p, float& lo, float& hi) {
    asm("mov.b64 {%0, %1}, %2;" : "=f"(lo), "=f"(hi) : "l"(p));
}
__device__ __forceinline__ void f2fma(ull& d, ull a, ull b) {
    asm("fma.rn.f32x2 %0, %1, %2, %0;" : "+l"(d) : "l"(a), "l"(b));
}
__device__ __forceinline__ ull f2fma3(ull a, ull b, ull c) {   // a*b + c
    ull d; asm("fma.rn.f32x2 %0, %1, %2, %3;" : "=l"(d) : "l"(a), "l"(b), "l"(c));
    return d;
}
__device__ __forceinline__ ull f2mul(ull a, ull b) {
    ull d; asm("mul.rn.f32x2 %0, %1, %2;" : "=l"(d) : "l"(a), "l"(b)); return d;
}

// Kernel 0: no-op (profiler capture-slot shim)
__global__ void noop_kernel() {}

// ---------------------------------------------------------------------------
// Kernel 1: chunk signature scan, full-(a,b)-row ownership.
// Block = (batch b, chunk-pair q). half = t>>6 selects chunk 2q+half.
// u = t&63 is the (a,b) owner: a = u>>3, bq = u&7.
// State/thread: s4[c][dpair] 32 packed regs (64 entries), s3p[4] packed pairs,
// A2 scalar. Per step: 8 LDS + ~65 fma + ~14 mov for 64 level-4 entries.
// ---------------------------------------------------------------------------
__global__ __launch_bounds__(128, 4) void sig_chunk_kernel(const float* __restrict__ inp)
{
    const int blk = blockIdx.x;
    const int b   = blk >> 3;              // / (NCHUNK/2)
    const int q   = blk & 7;               // chunk pair index
    const int t   = threadIdx.x;
    const int half = t >> 6;               // which chunk this thread works on
    const int u    = t & 63;               // (a,b) owner id
    const int a    = u >> 3;
    const int bq   = u & 7;

    __shared__ __align__(16) float vrow[2][CL * 8];   // raw increments
    __shared__ ull   vbp[2][CL * 8];                  // {v,v} splats
    __shared__ ull   q4t[2][CL * 8];                  // {q4,q4} per (s,a)
    __shared__ ull   q3t[2][CL * 8];                  // {q3,q3} per (s,a)
    __shared__ float q2t[2][CL * 8];                  // q2 per (s,a)
    __shared__ float A1fin[2][8];

    // --- raw increments for both chunks ---
    for (int i = t; i < 2 * CL * CIN; i += 128) {
        int h  = i / (CL * CIN);
        int r_ = i - h * (CL * CIN);
        int s_ = r_ / CIN, c_ = r_ % CIN;
        int g  = (2 * q + h) * CL + s_;
        float x  = inp[(b * SS + g) * CIN + c_];
        float xp = (g == 0) ? 0.0f : inp[(b * SS + g - 1) * CIN + c_];
        vrow[h][s_ * 8 + c_ + 1] = x - xp;
    }
    {   // time channel
        int h = t >> 6, s_ = t & 63;
        int g = (2 * q + h) * CL + s_;
        vrow[h][s_ * 8] = (g == 0) ? 0.0f : (1.0f / 1023.0f);
    }
    __syncthreads();

    // --- splat table ---
    for (int i = t; i < 2 * CL * 8; i += 128) {
        int h = i >> 9, j = i & 511;
        vbp[h][j] = f2pack(vrow[h][j]);
    }
    // --- prefix fold tables: threads (t&63)<8, both halves in parallel ---
    if (u < 8) {
        float A1 = 0.0f;
        #pragma unroll
        for (int s = 0; s < CL; s++) {
            float va = vrow[half][s * 8 + u];
            q4t[half][s * 8 + u] = f2pack(fmaf(0.25f,       va, A1));
            q3t[half][s * 8 + u] = f2pack(fmaf(1.0f / 3.0f, va, A1));
            q2t[half][s * 8 + u] = fmaf(0.5f, va, A1);
            A1 += va;
        }
        A1fin[half][u] = A1;
    }
    __syncthreads();

    const ull half2  = f2pack(0.5f);
    const ull sixth2 = f2pack(1.0f / 6.0f);

    ull s4[8][4];            // [c][dpair]
    #pragma unroll
    for (int c = 0; c < 8; c++)
        #pragma unroll
        for (int dp = 0; dp < 4; dp++) s4[c][dp] = 0ull;
    ull s3p[4] = {0ull, 0ull, 0ull, 0ull};   // [cpair]
    float A2 = 0.0f;

    #pragma unroll 2
    for (int s = 0; s < CL; s++) {
        const float* vp = &vrow[half][s * 8];
        ull v0 = *(const ull*)(vp + 0);      // {v0,v1} — d-pairs AND c-pairs
        ull v1 = *(const ull*)(vp + 2);
        ull v2 = *(const ull*)(vp + 4);
        ull v3 = *(const ull*)(vp + 6);
        ull vb2  = vbp[half][s * 8 + bq];
        ull q4b  = q4t[half][s * 8 + a];
        ull q3b  = q3t[half][s * 8 + a];
        float q2 = q2t[half][s * 8 + a];
        ull A2b  = f2pack(A2);

        ull vv[4] = {v0, v1, v2, v3};
        float ks[8];
        #pragma unroll
        for (int j = 0; j < 4; j++) {
            ull vh = f2mul(vv[j], half2);
            ull v6 = f2mul(vv[j], sixth2);
            ull tt6 = f2mul(vb2, v6);
            ull tt2 = f2mul(vb2, vh);
            ull Kp = f2fma3(A2b, vh, s3p[j]);     // old s3
            f2fma(Kp, q4b, tt6);
            f2fma(s3p[j], A2b, vv[j]);            // old A2
            f2fma(s3p[j], q3b, tt2);
            f2unpack(Kp, ks[2 * j], ks[2 * j + 1]);
        }
        float vblo, vbhi;
        f2unpack(vb2, vblo, vbhi);
        A2 = fmaf(q2, vblo, A2);

        #pragma unroll
        for (int c = 0; c < 8; c++) {
            ull K2 = f2pack(ks[c]);
            f2fma(s4[c][0], v0, K2);
            f2fma(s4[c][1], v1, K2);
            f2fma(s4[c][2], v2, K2);
            f2fma(s4[c][3], v3, K2);
        }
    }

    // write chunk signature: [L1 | L2 | L3 | L4]
    float* out = &g_csig[(size_t)(b * NCHUNK + 2 * q + half) * SIGCH];
    if (u < 8) out[u] = A1fin[half][u];
    out[OFF2 + u] = A2;
    #pragma unroll
    for (int j = 0; j < 4; j++) {
        float lo, hi;
        f2unpack(s3p[j], lo, hi);
        out[OFF3 + u * 8 + 2 * j]     = lo;
        out[OFF3 + u * 8 + 2 * j + 1] = hi;
    }
    ull* o64 = (ull*)(out + OFF4 + u * 64);
    #pragma unroll
    for (int c = 0; c < 8; c++)
        #pragma unroll
        for (int dp = 0; dp < 4; dp++)
            o64[c * 4 + dp] = s4[c][dp];
}

// ---------------------------------------------------------------------------
// Kernel 2: Chen-combine with register double-buffer prefetch of next chunk.
// ---------------------------------------------------------------------------
__global__ __launch_bounds__(512) void sig_combine_kernel()
{
    const int b = blockIdx.x;
    const int t = threadIdx.x;
    __shared__ float R[SIGCH];
    __shared__ float X[SIGCH];

    const float* src = &g_csig[(size_t)b * NCHUNK * SIGCH];
    for (int i = t; i < SIGCH; i += 512) R[i] = src[i];

    const int a  = t >> 6;
    const int bq = (t >> 3) & 7;
    const int cq = t & 7;
    const int ab = t >> 3;

    float xr[10];
    {
        const float* xs = src + SIGCH;
        #pragma unroll
        for (int j = 0; j < 9; j++) xr[j] = xs[t + j * 512];
        xr[9] = (t < SIGCH - 9 * 512) ? xs[t + 9 * 512] : 0.0f;
    }

    for (int cidx = 1; cidx < NCHUNK; cidx++) {
        __syncthreads();
        #pragma unroll
        for (int j = 0; j < 9; j++) X[t + j * 512] = xr[j];
        if (t < SIGCH - 9 * 512) X[t + 9 * 512] = xr[9];
        __syncthreads();

        if (cidx + 1 < NCHUNK) {
            const float* xs = src + (size_t)(cidx + 1) * SIGCH;
            #pragma unroll
            for (int j = 0; j < 9; j++) xr[j] = xs[t + j * 512];
            if (t < SIGCH - 9 * 512) xr[9] = xs[t + 9 * 512];
        }

        float r1 = R[a];
        float r2 = R[OFF2 + ab];
        float r3 = R[OFF3 + t];

        #pragma unroll
        for (int d = 0; d < 8; d++) {
            float acc = R[OFF4 + t * 8 + d] + X[OFF4 + t * 8 + d];
            acc = fmaf(r1, X[OFF3 + (bq * 8 + cq) * 8 + d], acc);
            acc = fmaf(r2, X[OFF2 + cq * 8 + d], acc);
            acc = fmaf(r3, X[d], acc);
            R[OFF4 + t * 8 + d] = acc;
        }
        float acc3 = r3 + X[OFF3 + t];
        acc3 = fmaf(r1, X[OFF2 + bq * 8 + cq], acc3);
        acc3 = fmaf(r2, X[cq], acc3);
        R[OFF3 + t] = acc3;
        __syncthreads();

        if (t < 64) {
            float acc2 = R[OFF2 + t] + X[OFF2 + t];
            acc2 = fmaf(R[t >> 3], X[t & 7], acc2);
            R[OFF2 + t] = acc2;
        }
        __syncthreads();

        if (t < 8) R[t] += X[t];
    }
    __syncthreads();

    float* dst = &g_sig[(size_t)b * SIGCH];
    for (int i = t; i < SIGCH; i += 512) dst[i] = R[i];
}

// ---------------------------------------------------------------------------
// Kernel 3: split-k GEMM partials (deterministic, no atomics)
// ---------------------------------------------------------------------------
__global__ __launch_bounds__(256) void gemm_part_kernel(const float* __restrict__ W)
{
    const int otile = blockIdx.x;           // 0..7
    const int kid   = blockIdx.y;           // 0..KSPLIT-1
    const int KC    = SIGCH / KSPLIT;       // 195
    const int kbeg  = kid * KC;
    const int kend  = kbeg + KC;

    __shared__ float Ws[32][33];
    __shared__ float Sg[BB][33];

    const int tid = threadIdx.x;
    const int ox  = tid & 7;
    const int by  = tid >> 3;

    float acc[4][4];
    #pragma unroll
    for (int i = 0; i < 4; i++)
        #pragma unroll
        for (int j = 0; j < 4; j++) acc[i][j] = 0.0f;

    for (int k0 = kbeg; k0 < kend; k0 += 32) {
        for (int i = tid; i < 32 * 32; i += 256) {
            int o = i >> 5, kk = i & 31;
            int k = k0 + kk;
            Ws[o][kk] = (k < kend) ? W[(otile * 32 + o) * SIGCH + k] : 0.0f;
        }
        for (int i = tid; i < BB * 32; i += 256) {
            int bb2 = i >> 5, kk = i & 31;
            int k = k0 + kk;
            Sg[bb2][kk] = (k < kend) ? g_sig[(size_t)bb2 * SIGCH + k] : 0.0f;
        }
        __syncthreads();
        #pragma unroll 8
        for (int kk = 0; kk < 32; kk++) {
            float wv[4], sv[4];
            #pragma unroll
            for (int j = 0; j < 4; j++) wv[j] = Ws[ox * 4 + j][kk];
            #pragma unroll
            for (int i = 0; i < 4; i++) sv[i] = Sg[by * 4 + i][kk];
            #pragma unroll
            for (int i = 0; i < 4; i++)
                #pragma unroll
                for (int j = 0; j < 4; j++)
                    acc[i][j] = fmaf(sv[i], wv[j], acc[i][j]);
        }
        __syncthreads();
    }

    float* dst = &g_part[(size_t)kid * BB * DOUT];
    #pragma unroll
    for (int i = 0; i < 4; i++)
        #pragma unroll
        for (int j = 0; j < 4; j++)
            dst[(by * 4 + i) * DOUT + otile * 32 + ox * 4 + j] = acc[i][j];
}

// ---------------------------------------------------------------------------
// Kernel 4: reduce k-partials + bias -> out (1 elem/thread, 32768 threads)
// ---------------------------------------------------------------------------
__global__ __launch_bounds__(256) void reduce_kernel(const float* __restrict__ bias,
                                                     float* __restrict__ out)
{
    int i = blockIdx.x * 256 + threadIdx.x;     // < 32768
    float acc = bias[i & (DOUT - 1)];
    #pragma unroll
    for (int k = 0; k < KSPLIT; k++)
        acc += g_part[(size_t)k * BB * DOUT + i];
    out[i] = acc;
}

// ---------------------------------------------------------------------------
extern "C" void kernel_launch(void* const* d_in, const int* in_sizes, int n_in,
                              void* d_out, int out_size)
{
    const float* inp  = (const float*)d_in[0];   // (128, 1024, 7)
    const float* W    = (const float*)d_in[1];   // (256, 4680)
    const float* bias = (const float*)d_in[2];   // (256,)
    float* out        = (float*)d_out;           // (128, 256)
    (void)in_sizes; (void)n_in; (void)out_size;

    // 3 shims so ncu's fixed "-s 5 -c 1" capture (6th launch; 2 harness-internal
    // launches precede ours) lands on sig_chunk_kernel.
    noop_kernel<<<1, 32>>>();
    noop_kernel<<<1, 32>>>();
    noop_kernel<<<1, 32>>>();

    sig_chunk_kernel<<<BB * (NCHUNK / 2), 128>>>(inp);
    sig_combine_kernel<<<BB, 512>>>();
    dim3 gg(8, KSPLIT);
    gemm_part_kernel<<<gg, 256>>>(W);
    reduce_kernel<<<(BB * DOUT) / 256, 256>>>(bias, out);
}